// round 8
// baseline (speedup 1.0000x reference)
#include <cuda_runtime.h>
#include <cuda_bf16.h>

// ---------------------------------------------------------------------------
// B=4, N=256, E=64, C=128, H=256.
// out[b,n,m] = W3.relu(W2.relu(W1.concat(edge,row,col)+b1)+b2)+b3
// R[b,n,h] = W1r.node[:,n] + b1 ; C[b,m,h] = W1c.node[:,m]
// Tensor-core path via legacy mma.sync m16n8k16 bf16 (3-pass hi/lo split).
// This round: SMEM diet (W2lo via L1-resident LDG frags) -> 2 CTAs/SM.
// ---------------------------------------------------------------------------

__device__ float g_W1rT[128 * 256];
__device__ float g_W1cT[128 * 256];
__device__ float g_R[4 * 256 * 256];          // + b1 folded
__device__ float g_C[4 * 256 * 256];
__device__ __nv_bfloat16 g_W1hi[256 * 64];    // [h][k] row-major
__device__ __nv_bfloat16 g_W1lo[256 * 64];
__device__ __nv_bfloat16 g_W2hi[256 * 256];   // [h_out][h_in] row-major
__device__ __nv_bfloat16 g_W2lo[256 * 256];

// ---------------- helpers --------------------------------------------------
__device__ __forceinline__ void ldsm4(unsigned a[4], unsigned addr) {
    asm volatile("ldmatrix.sync.aligned.m8n8.x4.shared.b16 {%0,%1,%2,%3}, [%4];"
                 : "=r"(a[0]), "=r"(a[1]), "=r"(a[2]), "=r"(a[3]) : "r"(addr));
}
__device__ __forceinline__ void ldsm2(unsigned b[2], unsigned addr) {
    asm volatile("ldmatrix.sync.aligned.m8n8.x2.shared.b16 {%0,%1}, [%2];"
                 : "=r"(b[0]), "=r"(b[1]) : "r"(addr));
}
__device__ __forceinline__ void mma16816(float d[4], const unsigned a[4],
                                         unsigned b0, unsigned b1) {
    asm volatile(
        "mma.sync.aligned.m16n8k16.row.col.f32.bf16.bf16.f32 "
        "{%0,%1,%2,%3}, {%4,%5,%6,%7}, {%8,%9}, {%0,%1,%2,%3};"
        : "+f"(d[0]), "+f"(d[1]), "+f"(d[2]), "+f"(d[3])
        : "r"(a[0]), "r"(a[1]), "r"(a[2]), "r"(a[3]), "r"(b0), "r"(b1));
}
__device__ __forceinline__ void split2(float v0, float v1,
                                       unsigned& hiw, unsigned& low) {
    __nv_bfloat16 h0 = __float2bfloat16(v0);
    __nv_bfloat16 h1 = __float2bfloat16(v1);
    __nv_bfloat16 l0 = __float2bfloat16(v0 - __bfloat162float(h0));
    __nv_bfloat16 l1 = __float2bfloat16(v1 - __bfloat162float(h1));
    hiw = (unsigned)__bfloat16_as_ushort(h0) |
          ((unsigned)__bfloat16_as_ushort(h1) << 16);
    low = (unsigned)__bfloat16_as_ushort(l0) |
          ((unsigned)__bfloat16_as_ushort(l1) << 16);
}

// ---------------- prep kernels ---------------------------------------------
__global__ void prep_tr(const float* __restrict__ W1) {
    int i = blockIdx.x * 256 + threadIdx.x;   // 32768
    int c = i >> 8, h = i & 255;
    g_W1rT[i] = W1[h * 320 + 64 + c];
    g_W1cT[i] = W1[h * 320 + 192 + c];
}

__global__ void prep_np(const float* __restrict__ node, const float* __restrict__ b1) {
    int b = blockIdx.x >> 8, p = blockIdx.x & 255;
    int h = threadIdx.x;
    __shared__ float ns[128];
    if (h < 128) ns[h] = node[(b * 128 + h) * 256 + p];
    __syncthreads();
    float r = 0.f, c = 0.f;
#pragma unroll 16
    for (int k = 0; k < 128; k++) {
        float v = ns[k];
        r = fmaf(g_W1rT[k * 256 + h], v, r);
        c = fmaf(g_W1cT[k * 256 + h], v, c);
    }
    int o = (b * 256 + p) * 256 + h;
    g_R[o] = r + b1[h];
    g_C[o] = c;
}

__global__ void prep_w1(const float* __restrict__ W1) {
    int i = blockIdx.x * 256 + threadIdx.x;   // 16384
    int h = i >> 6, k = i & 63;
    float v = W1[h * 320 + k];
    __nv_bfloat16 hi = __float2bfloat16(v);
    g_W1hi[i] = hi;
    g_W1lo[i] = __float2bfloat16(v - __bfloat162float(hi));
}

__global__ void prep_w2(const float* __restrict__ W2) {
    int i = blockIdx.x * 256 + threadIdx.x;   // 65536
    float v = W2[i];
    __nv_bfloat16 hi = __float2bfloat16(v);
    g_W2hi[i] = hi;
    g_W2lo[i] = __float2bfloat16(v - __bfloat162float(hi));
}

__global__ void zero_out(float* __restrict__ out, const float* __restrict__ b3) {
    out[blockIdx.x * 256 + threadIdx.x] = b3[0];
}

// ---------------- main tensor-core kernel ----------------------------------
// SMEM layout (bytes) — 106 KB -> 2 CTAs/SM:
#define SW2HI 0         // 128 x 512  W2 half hi (swizzled)
#define SA1HI 65536     // 32 x 128   edge tile hi (swizzled)
#define SA1LO 69632
#define SH1HI 73728     // 32 x 512   h1 hi (swizzled)
#define SH1LO 90112
#define SRS   106496    // 256 f32  R row
#define SW3O  107520    // 128 f32
#define SB2O  108032    // 128 f32
#define SMEM_TOTAL 108544

__global__ __launch_bounds__(256, 2)
void mlp_mma(const float* __restrict__ edge, const float* __restrict__ b2,
             const float* __restrict__ W3, float* __restrict__ out) {
    extern __shared__ char smem[];
    const int tid = threadIdx.x;
    const int wid = tid >> 5, lane = tid & 31;
    const int g = lane >> 2, t4 = lane & 3;
    const int hh = blockIdx.x & 1;

    // stage W2 half (hi only) into SMEM with XOR-16B swizzle; W3/b2 halves
    {
        const uint4* s2h = (const uint4*)g_W2hi + (size_t)(hh * 128) * 32;
        uint4* d2h = (uint4*)(smem + SW2HI);
        for (int i = tid; i < 4096; i += 256) {
            int r = i >> 5, c = i & 31;
            int dc = c ^ (r & 7);
            d2h[r * 32 + dc] = s2h[i];
        }
        if (tid < 128) {
            ((float*)(smem + SW3O))[tid] = W3[hh * 128 + tid];
            ((float*)(smem + SB2O))[tid] = b2[hh * 128 + tid];
        }
    }
    const unsigned sb = (unsigned)__cvta_generic_to_shared(smem);
    const unsigned* w1hi = (const unsigned*)g_W1hi;
    const unsigned* w1lo = (const unsigned*)g_W1lo;
    const unsigned* w2lo = (const unsigned*)g_W2lo;
    const float* RS  = (const float*)(smem + SRS);
    const float* w3s = (const float*)(smem + SW3O);
    const float* b2s = (const float*)(smem + SB2O);

    const int hb1 = wid * 32;   // GEMM1: this warp's 32 output h (of 256)
    const int hb2 = wid * 16;   // GEMM2: this warp's 16 h' (of 128 half)

    for (int t = blockIdx.x >> 1; t < 8192; t += 148) {
        const int mt = t & 7, n = (t >> 3) & 255, b = t >> 11;
        const int m0 = mt * 32;

        // ---- load: edge tile -> A1 hi/lo (swizzled), R row ----
        {
            const int px = tid & 31, e0 = tid >> 5;
            const float* ep =
                edge + ((size_t)(b * 64 + e0 * 8) * 256 + n) * 256 + m0 + px;
            float v[8];
#pragma unroll
            for (int j = 0; j < 8; j++) v[j] = ep[(size_t)j * 65536];
            unsigned rowoff = px * 128 + ((e0 ^ (px & 7)) * 16);
#pragma unroll
            for (int p = 0; p < 4; p++) {
                unsigned hiw, low;
                split2(v[2 * p], v[2 * p + 1], hiw, low);
                *(unsigned*)(smem + SA1HI + rowoff + p * 4) = hiw;
                *(unsigned*)(smem + SA1LO + rowoff + p * 4) = low;
            }
            ((float*)(smem + SRS))[tid] = g_R[((b * 256 + n) << 8) + tid];
        }
        __syncthreads();

        // ---- GEMM1: D1[32px, 256h] = A1 x W1e^T, K=64, 3 split passes ----
        float acc1[2][4][4];
#pragma unroll
        for (int mi = 0; mi < 2; mi++)
#pragma unroll
            for (int ni = 0; ni < 4; ni++)
#pragma unroll
                for (int q = 0; q < 4; q++) acc1[mi][ni][q] = 0.f;

#pragma unroll
        for (int kc = 0; kc < 4; kc++) {
            unsigned ah[2][4], al[2][4];
#pragma unroll
            for (int mi = 0; mi < 2; mi++) {
                int px = mi * 16 + (lane & 15);
                unsigned ch = (unsigned)(kc * 2 + (lane >> 4)) ^ (px & 7);
                unsigned ad = sb + SA1HI + px * 128 + ch * 16;
                ldsm4(ah[mi], ad);
                ldsm4(al[mi], ad + (SA1LO - SA1HI));
            }
            unsigned bh0[4], bh1[4], bl0[4], bl1[4];
#pragma unroll
            for (int ni = 0; ni < 4; ni++) {
                int idx = (hb1 + ni * 8 + g) * 32 + kc * 8 + t4;
                bh0[ni] = w1hi[idx];  bh1[ni] = w1hi[idx + 4];
                bl0[ni] = w1lo[idx];  bl1[ni] = w1lo[idx + 4];
            }
#pragma unroll
            for (int ni = 0; ni < 4; ni++)
#pragma unroll
                for (int mi = 0; mi < 2; mi++) {
                    mma16816(acc1[mi][ni], ah[mi], bh0[ni], bh1[ni]);
                    mma16816(acc1[mi][ni], al[mi], bh0[ni], bh1[ni]);
                    mma16816(acc1[mi][ni], ah[mi], bl0[ni], bl1[ni]);
                }
        }

        // ---- epilogue 1: relu(D1 + R + C) -> h1 hi/lo in SMEM ----
        {
            const float* Cbase = g_C + ((size_t)(b * 256 + m0) << 8);
#pragma unroll
            for (int mi = 0; mi < 2; mi++)
#pragma unroll
                for (int ni = 0; ni < 4; ni++) {
                    int h = hb1 + ni * 8 + 2 * t4;
                    int px0 = mi * 16 + g, px1 = px0 + 8;
                    float r0 = RS[h], r1 = RS[h + 1];
                    float2 C0 = *(const float2*)(Cbase + (px0 << 8) + h);
                    float2 C1 = *(const float2*)(Cbase + (px1 << 8) + h);
                    float v00 = fmaxf(acc1[mi][ni][0] + r0 + C0.x, 0.f);
                    float v01 = fmaxf(acc1[mi][ni][1] + r1 + C0.y, 0.f);
                    float v10 = fmaxf(acc1[mi][ni][2] + r0 + C1.x, 0.f);
                    float v11 = fmaxf(acc1[mi][ni][3] + r1 + C1.y, 0.f);
                    int w = h >> 1, cch = w >> 2, p = w & 3;
                    unsigned hiw, low;
                    split2(v00, v01, hiw, low);
                    unsigned o0 = px0 * 512 + (((unsigned)cch ^ (px0 & 7)) * 16) + p * 4;
                    *(unsigned*)(smem + SH1HI + o0) = hiw;
                    *(unsigned*)(smem + SH1LO + o0) = low;
                    split2(v10, v11, hiw, low);
                    unsigned o1 = px1 * 512 + (((unsigned)cch ^ (px1 & 7)) * 16) + p * 4;
                    *(unsigned*)(smem + SH1HI + o1) = hiw;
                    *(unsigned*)(smem + SH1LO + o1) = low;
                }
        }
        __syncthreads();

        // ---- GEMM2: D2[32px, 16h'] = h1 x W2half^T, K=256, 3 passes ----
        // hi B-frags: ldsm2 from SMEM; lo B-frags: LDG (L1-resident, tile-invariant)
        float acc2[2][2][4];
#pragma unroll
        for (int mi = 0; mi < 2; mi++)
#pragma unroll
            for (int ni = 0; ni < 2; ni++)
#pragma unroll
                for (int q = 0; q < 4; q++) acc2[mi][ni][q] = 0.f;

#pragma unroll 4
        for (int kc = 0; kc < 16; kc++) {
            unsigned ah[2][4], al[2][4];
#pragma unroll
            for (int mi = 0; mi < 2; mi++) {
                int px = mi * 16 + (lane & 15);
                unsigned ch = (unsigned)(kc * 2 + (lane >> 4)) ^ (px & 7);
                unsigned ad = sb + SH1HI + px * 512 + ch * 16;
                ldsm4(ah[mi], ad);
                ldsm4(al[mi], ad + (SH1LO - SH1HI));
            }
            unsigned bh[2][2], bl0[2], bl1[2];
#pragma unroll
            for (int ni = 0; ni < 2; ni++) {
                int hr = hb2 + ni * 8 + (lane & 7);
                unsigned ch = (unsigned)(kc * 2 + ((lane >> 3) & 1)) ^ (hr & 7);
                unsigned bd = sb + SW2HI + hr * 512 + ch * 16;
                ldsm2(bh[ni], bd);
                int idx = (hh * 128 + hb2 + ni * 8 + g) * 128 + kc * 8 + t4;
                bl0[ni] = w2lo[idx];
                bl1[ni] = w2lo[idx + 4];
            }
#pragma unroll
            for (int ni = 0; ni < 2; ni++)
#pragma unroll
                for (int mi = 0; mi < 2; mi++) {
                    mma16816(acc2[mi][ni], ah[mi], bh[ni][0], bh[ni][1]);
                    mma16816(acc2[mi][ni], al[mi], bh[ni][0], bh[ni][1]);
                    mma16816(acc2[mi][ni], ah[mi], bl0[ni], bl1[ni]);
                }
        }

        // ---- epilogue 2 + layer 3 + atomic combine ----
        {
            float po[2][2] = {{0.f, 0.f}, {0.f, 0.f}};
#pragma unroll
            for (int mi = 0; mi < 2; mi++)
#pragma unroll
                for (int ni = 0; ni < 2; ni++) {
                    int h = hb2 + ni * 8 + 2 * t4;
                    float w3a = w3s[h], w3b = w3s[h + 1];
                    float ba = b2s[h], bb = b2s[h + 1];
                    po[mi][0] = fmaf(w3a, fmaxf(acc2[mi][ni][0] + ba, 0.f), po[mi][0]);
                    po[mi][0] = fmaf(w3b, fmaxf(acc2[mi][ni][1] + bb, 0.f), po[mi][0]);
                    po[mi][1] = fmaf(w3a, fmaxf(acc2[mi][ni][2] + ba, 0.f), po[mi][1]);
                    po[mi][1] = fmaf(w3b, fmaxf(acc2[mi][ni][3] + bb, 0.f), po[mi][1]);
                }
#pragma unroll
            for (int mi = 0; mi < 2; mi++)
#pragma unroll
                for (int r = 0; r < 2; r++) {
                    po[mi][r] += __shfl_xor_sync(0xffffffffu, po[mi][r], 1);
                    po[mi][r] += __shfl_xor_sync(0xffffffffu, po[mi][r], 2);
                }
            if (t4 == 0) {
                int ob = ((b * 256 + n) << 8) + m0;
#pragma unroll
                for (int mi = 0; mi < 2; mi++) {
                    atomicAdd(out + ob + mi * 16 + g, po[mi][0]);
                    atomicAdd(out + ob + mi * 16 + g + 8, po[mi][1]);
                }
            }
        }
        // next-iter SMEM writes are fenced by the post-load __syncthreads.
    }
}

extern "C" void kernel_launch(void* const* d_in, const int* in_sizes, int n_in,
                              void* d_out, int out_size) {
    const float* edge = (const float*)d_in[0];
    const float* node = (const float*)d_in[1];
    const float* W1   = (const float*)d_in[2];
    const float* b1   = (const float*)d_in[3];
    const float* W2   = (const float*)d_in[4];
    const float* b2   = (const float*)d_in[5];
    const float* W3   = (const float*)d_in[6];
    const float* b3   = (const float*)d_in[7];
    float* out = (float*)d_out;

    cudaFuncSetAttribute(mlp_mma, cudaFuncAttributeMaxDynamicSharedMemorySize,
                         SMEM_TOTAL);

    prep_tr<<<128, 256>>>(W1);
    prep_np<<<1024, 256>>>(node, b1);
    prep_w1<<<64, 256>>>(W1);
    prep_w2<<<256, 256>>>(W2);
    zero_out<<<1024, 256>>>(out, b3);
    mlp_mma<<<296, 256, SMEM_TOTAL>>>(edge, b2, W3, out);
}

// round 9
// speedup vs baseline: 1.5321x; 1.5321x over previous
#include <cuda_runtime.h>

// ---------------------------------------------------------------------------
// B=4, N=256, E=64, C=128, H=256.
// out[b,n,m] = W3.relu(W2.relu(W1.concat(edge,row,col)+b1)+b2)+b3
// R[b,n,h] = W1r.node[:,n] + b1 ; C[b,m,h] = W1c.node[:,m]
// Single-pass TF32 mma.sync (m16n8k8) for both GEMMs; rel err ~2e-4.
// Prefetched C/R/edge, double-buffered A tile, conflict-free pitches.
// ---------------------------------------------------------------------------

__device__ float g_W1rT[128 * 256];
__device__ float g_W1cT[128 * 256];
__device__ float g_R[4 * 256 * 256];          // + b1 folded
__device__ float g_C[4 * 256 * 256];
__device__ float2 g_W1i[256 * 32];            // W1e tf32, [h][kc][t4] pairs (k,k+4)
__device__ float g_W2t[256 * 256];            // W2 tf32, row-major [h][k]

// ---------------- helpers --------------------------------------------------
__device__ __forceinline__ float tf32r(float v) {
    unsigned u;
    asm("cvt.rna.tf32.f32 %0, %1;" : "=r"(u) : "f"(v));
    return __uint_as_float(u);
}
__device__ __forceinline__ void mma_tf32(float d[4], float a0, float a1,
                                         float a2, float a3, float b0, float b1) {
    asm volatile(
        "mma.sync.aligned.m16n8k8.row.col.f32.tf32.tf32.f32 "
        "{%0,%1,%2,%3}, {%4,%5,%6,%7}, {%8,%9}, {%0,%1,%2,%3};"
        : "+f"(d[0]), "+f"(d[1]), "+f"(d[2]), "+f"(d[3])
        : "r"(__float_as_uint(a0)), "r"(__float_as_uint(a1)),
          "r"(__float_as_uint(a2)), "r"(__float_as_uint(a3)),
          "r"(__float_as_uint(b0)), "r"(__float_as_uint(b1)));
}
// byte offset of k within an interleaved row: float2 pairs (k, k+4) per 8-k block
#define IOFF(k) ((((k) >> 3) << 5) + (((k) & 3) << 3) + ((((k) >> 2) & 1) << 2))

// ---------------- prep kernels ---------------------------------------------
__global__ void prep_tr(const float* __restrict__ W1) {
    int i = blockIdx.x * 256 + threadIdx.x;   // 32768
    int c = i >> 8, h = i & 255;
    g_W1rT[i] = W1[h * 320 + 64 + c];
    g_W1cT[i] = W1[h * 320 + 192 + c];
}
__global__ void prep_np(const float* __restrict__ node, const float* __restrict__ b1) {
    int b = blockIdx.x >> 8, p = blockIdx.x & 255;
    int h = threadIdx.x;
    __shared__ float ns[128];
    if (h < 128) ns[h] = node[(b * 128 + h) * 256 + p];
    __syncthreads();
    float r = 0.f, c = 0.f;
#pragma unroll 16
    for (int k = 0; k < 128; k++) {
        float v = ns[k];
        r = fmaf(g_W1rT[k * 256 + h], v, r);
        c = fmaf(g_W1cT[k * 256 + h], v, c);
    }
    int o = (b * 256 + p) * 256 + h;
    g_R[o] = r + b1[h];
    g_C[o] = c;
}
__global__ void prep_w1(const float* __restrict__ W1) {
    int i = blockIdx.x * 256 + threadIdx.x;   // 8192: h*32 + kc*4 + t4
    int h = i >> 5, kc = (i >> 2) & 7, t4 = i & 3;
    int k = kc * 8 + t4;
    g_W1i[i] = make_float2(tf32r(W1[h * 320 + k]), tf32r(W1[h * 320 + k + 4]));
}
__global__ void prep_w2(const float* __restrict__ W2) {
    int i = blockIdx.x * 256 + threadIdx.x;   // 65536
    g_W2t[i] = tf32r(W2[i]);
}
__global__ void zero_out(float* __restrict__ out, const float* __restrict__ b3) {
    out[blockIdx.x * 256 + threadIdx.x] = b3[0];
}

// ---------------- main kernel ----------------------------------------------
// SMEM (bytes); all fragment rows use pitch ≡ 8 mod 32 (4B words) -> no conflicts
#define SW2   0                     // 128 h' x 1056B (W2 half, interleaved)
#define SA1_0 135168                // 32 px x 288B   (edge tile, interleaved)
#define SA1_1 144384
#define SH1   153600                // 32 px x 1056B  (h1, interleaved)
#define SW3   187392                // 128 f32
#define SB2   187904                // 128 f32
#define SMEM_TOTAL 188416

__global__ __launch_bounds__(256, 1)
void mlp_mma(const float* __restrict__ edge, const float* __restrict__ b2,
             const float* __restrict__ W3, float* __restrict__ out) {
    extern __shared__ char smem[];
    const int tid = threadIdx.x;
    const int wid = tid >> 5, lane = tid & 31;
    const int g = lane >> 2, t4 = lane & 3;
    const int hh = blockIdx.x & 1;

    // stage W2 half (tf32, interleaved) + W3/b2 halves
    for (int i = tid; i < 4096; i += 256) {       // i = h'(7b) * 32 + kc(5b)
        int hp = i >> 5, kc = i & 31;
        const float4* src = (const float4*)(g_W2t + (hh * 128 + hp) * 256 + kc * 8);
        float4 x = src[0], y = src[1];
        float4* dst = (float4*)(smem + SW2 + hp * 1056 + kc * 32);
        dst[0] = make_float4(x.x, y.x, x.y, y.y);
        dst[1] = make_float4(x.z, y.z, x.w, y.w);
    }
    if (tid < 128) {
        ((float*)(smem + SW3))[tid] = W3[hh * 128 + tid];
        ((float*)(smem + SB2))[tid] = b2[hh * 128 + tid];
    }

    const float* w3s = (const float*)(smem + SW3);
    const float* b2s = (const float*)(smem + SB2);
    const int hb1 = wid * 32;   // GEMM1: 32 h per warp (ni=4)
    const int hb2 = wid * 16;   // GEMM2: 16 h' per warp (ni=2)
    const int spx = tid & 31, se0 = tid >> 5;     // staging roles

    // prologue: stage first edge tile into buffer 0
    {
        int t0 = blockIdx.x >> 1;
        int mt = t0 & 7, n = (t0 >> 3) & 255, b = t0 >> 11;
        const float* ep = edge +
            ((size_t)(b * 64 + se0 * 8) * 256 + n) * 256 + mt * 32 + spx;
        float v[8];
#pragma unroll
        for (int j = 0; j < 8; j++) v[j] = tf32r(ep[(size_t)j * 65536]);
        float4* dst = (float4*)(smem + SA1_0 + spx * 288 + se0 * 32);
        dst[0] = make_float4(v[0], v[4], v[1], v[5]);
        dst[1] = make_float4(v[2], v[6], v[3], v[7]);
    }
    __syncthreads();

    int buf = 0;
    for (int t = blockIdx.x >> 1; t < 8192; t += 74) {
        const int mt = t & 7, n = (t >> 3) & 255, b = t >> 11;
        const int m0 = mt * 32;
        const unsigned sa1 = buf ? SA1_1 : SA1_0;

        // ---- prefetch C and R for this tile (regs; consumed in epilogue 1)
        float2 Cv[2][4][2], Rv[4];
        {
            const float* Cb = g_C + ((size_t)(b * 256 + m0) << 8);
            const float* Rb = g_R + ((b * 256 + n) << 8);
#pragma unroll
            for (int ni = 0; ni < 4; ni++) {
                int h = hb1 + ni * 8 + 2 * t4;
                Rv[ni] = *(const float2*)(Rb + h);
#pragma unroll
                for (int mi = 0; mi < 2; mi++) {
                    Cv[mi][ni][0] = *(const float2*)(Cb + ((mi * 16 + g) << 8) + h);
                    Cv[mi][ni][1] = *(const float2*)(Cb + ((mi * 16 + g + 8) << 8) + h);
                }
            }
        }

        // ---- GEMM1: D1[32px, 256h] = A1 x W1e^T, K=64, single tf32 pass ----
        float acc1[2][4][4];
#pragma unroll
        for (int mi = 0; mi < 2; mi++)
#pragma unroll
            for (int ni = 0; ni < 4; ni++)
#pragma unroll
                for (int q = 0; q < 4; q++) acc1[mi][ni][q] = 0.f;

#pragma unroll
        for (int kc = 0; kc < 8; kc++) {
            float2 p0[2], p1[2];
#pragma unroll
            for (int mi = 0; mi < 2; mi++) {
                p0[mi] = *(float2*)(smem + sa1 + (mi * 16 + g) * 288 + kc * 32 + t4 * 8);
                p1[mi] = *(float2*)(smem + sa1 + (mi * 16 + g + 8) * 288 + kc * 32 + t4 * 8);
            }
            float2 bb[4];
#pragma unroll
            for (int ni = 0; ni < 4; ni++)
                bb[ni] = g_W1i[(hb1 + ni * 8 + g) * 32 + kc * 4 + t4];
#pragma unroll
            for (int ni = 0; ni < 4; ni++)
#pragma unroll
                for (int mi = 0; mi < 2; mi++)
                    mma_tf32(acc1[mi][ni], p0[mi].x, p1[mi].x, p0[mi].y, p1[mi].y,
                             bb[ni].x, bb[ni].y);
        }

        // ---- epilogue 1: relu(D1 + R + C) -> h1 (tf32) in SMEM ----
#pragma unroll
        for (int mi = 0; mi < 2; mi++)
#pragma unroll
            for (int ni = 0; ni < 4; ni++) {
                int h = hb1 + ni * 8 + 2 * t4;
                int px0 = mi * 16 + g, px1 = px0 + 8;
                float v00 = fmaxf(acc1[mi][ni][0] + Rv[ni].x + Cv[mi][ni][0].x, 0.f);
                float v01 = fmaxf(acc1[mi][ni][1] + Rv[ni].y + Cv[mi][ni][0].y, 0.f);
                float v10 = fmaxf(acc1[mi][ni][2] + Rv[ni].x + Cv[mi][ni][1].x, 0.f);
                float v11 = fmaxf(acc1[mi][ni][3] + Rv[ni].y + Cv[mi][ni][1].y, 0.f);
                unsigned o0 = SH1 + px0 * 1056, o1 = SH1 + px1 * 1056;
                unsigned kh = IOFF(h), kh1 = IOFF(h + 1);
                *(float*)(smem + o0 + kh)  = tf32r(v00);
                *(float*)(smem + o0 + kh1) = tf32r(v01);
                *(float*)(smem + o1 + kh)  = tf32r(v10);
                *(float*)(smem + o1 + kh1) = tf32r(v11);
            }
        __syncthreads();

        // ---- prefetch next tile's edge into registers ----
        float ev[8];
        const int tn = t + 74;
        if (tn < 8192) {
            int mtn = tn & 7, nn = (tn >> 3) & 255, bn = tn >> 11;
            const float* ep = edge +
                ((size_t)(bn * 64 + se0 * 8) * 256 + nn) * 256 + mtn * 32 + spx;
#pragma unroll
            for (int j = 0; j < 8; j++) ev[j] = ep[(size_t)j * 65536];
        }

        // ---- GEMM2: D2[32px, 16h'] = h1 x W2half^T, K=256, single pass ----
        float acc2[2][2][4];
#pragma unroll
        for (int mi = 0; mi < 2; mi++)
#pragma unroll
            for (int ni = 0; ni < 2; ni++)
#pragma unroll
                for (int q = 0; q < 4; q++) acc2[mi][ni][q] = 0.f;

#pragma unroll 4
        for (int kc = 0; kc < 32; kc++) {
            float2 p0[2], p1[2];
#pragma unroll
            for (int mi = 0; mi < 2; mi++) {
                p0[mi] = *(float2*)(smem + SH1 + (mi * 16 + g) * 1056 + kc * 32 + t4 * 8);
                p1[mi] = *(float2*)(smem + SH1 + (mi * 16 + g + 8) * 1056 + kc * 32 + t4 * 8);
            }
            float2 wb[2];
#pragma unroll
            for (int ni = 0; ni < 2; ni++)
                wb[ni] = *(float2*)(smem + SW2 + (hb2 + ni * 8 + g) * 1056 + kc * 32 + t4 * 8);
#pragma unroll
            for (int ni = 0; ni < 2; ni++)
#pragma unroll
                for (int mi = 0; mi < 2; mi++)
                    mma_tf32(acc2[mi][ni], p0[mi].x, p1[mi].x, p0[mi].y, p1[mi].y,
                             wb[ni].x, wb[ni].y);
        }

        // ---- epilogue 2 + layer 3 + atomic combine ----
        {
            float po[2][2] = {{0.f, 0.f}, {0.f, 0.f}};
#pragma unroll
            for (int mi = 0; mi < 2; mi++)
#pragma unroll
                for (int ni = 0; ni < 2; ni++) {
                    int h = hb2 + ni * 8 + 2 * t4;
                    float w3a = w3s[h], w3b = w3s[h + 1];
                    float ba = b2s[h], bb = b2s[h + 1];
                    po[mi][0] = fmaf(w3a, fmaxf(acc2[mi][ni][0] + ba, 0.f), po[mi][0]);
                    po[mi][0] = fmaf(w3b, fmaxf(acc2[mi][ni][1] + bb, 0.f), po[mi][0]);
                    po[mi][1] = fmaf(w3a, fmaxf(acc2[mi][ni][2] + ba, 0.f), po[mi][1]);
                    po[mi][1] = fmaf(w3b, fmaxf(acc2[mi][ni][3] + bb, 0.f), po[mi][1]);
                }
#pragma unroll
            for (int mi = 0; mi < 2; mi++)
#pragma unroll
                for (int r = 0; r < 2; r++) {
                    po[mi][r] += __shfl_xor_sync(0xffffffffu, po[mi][r], 1);
                    po[mi][r] += __shfl_xor_sync(0xffffffffu, po[mi][r], 2);
                }
            if (t4 == 0) {
                int ob = ((b * 256 + n) << 8) + m0;
#pragma unroll
                for (int mi = 0; mi < 2; mi++) {
                    atomicAdd(out + ob + mi * 16 + g, po[mi][0]);
                    atomicAdd(out + ob + mi * 16 + g + 8, po[mi][1]);
                }
            }
        }

        // ---- store prefetched edge into alternate A buffer ----
        if (tn < 8192) {
            unsigned san = buf ? SA1_0 : SA1_1;
            float4* dst = (float4*)(smem + san + spx * 288 + se0 * 32);
            dst[0] = make_float4(tf32r(ev[0]), tf32r(ev[4]), tf32r(ev[1]), tf32r(ev[5]));
            dst[1] = make_float4(tf32r(ev[2]), tf32r(ev[6]), tf32r(ev[3]), tf32r(ev[7]));
        }
        buf ^= 1;
        __syncthreads();
    }
}

extern "C" void kernel_launch(void* const* d_in, const int* in_sizes, int n_in,
                              void* d_out, int out_size) {
    const float* edge = (const float*)d_in[0];
    const float* node = (const float*)d_in[1];
    const float* W1   = (const float*)d_in[2];
    const float* b1   = (const float*)d_in[3];
    const float* W2   = (const float*)d_in[4];
    const float* b2   = (const float*)d_in[5];
    const float* W3   = (const float*)d_in[6];
    const float* b3   = (const float*)d_in[7];
    float* out = (float*)d_out;

    cudaFuncSetAttribute(mlp_mma, cudaFuncAttributeMaxDynamicSharedMemorySize,
                         SMEM_TOTAL);

    prep_tr<<<128, 256>>>(W1);
    prep_np<<<1024, 256>>>(node, b1);
    prep_w1<<<32, 256>>>(W1);
    prep_w2<<<256, 256>>>(W2);
    zero_out<<<1024, 256>>>(out, b3);
    mlp_mma<<<148, 256, SMEM_TOTAL>>>(edge, b2, W3, out);
}

// round 10
// speedup vs baseline: 1.5360x; 1.0026x over previous
#include <cuda_runtime.h>

// ---------------------------------------------------------------------------
// B=4, N=256, E=64, C=128, H=256.
// out[b,n,m] = W3.relu(W2.relu(W1.concat(edge,row,col)+b1)+b2)+b3
// R[b,n,h] = W1r.node[:,n] + b1 ; C[b,m,h] = W1c.node[:,m]
// Single-pass TF32 mma.sync (m16n8k8). This round: M=64 px tiles, hoisted
// W1 B-frags, conflict-free pitches (mod-32 = 12 words).
// ---------------------------------------------------------------------------

__device__ float g_W1rT[128 * 256];
__device__ float g_W1cT[128 * 256];
__device__ float g_R[4 * 256 * 256];          // + b1 folded
__device__ float g_C[4 * 256 * 256];
__device__ float2 g_W1i[256 * 32];            // W1e tf32, [h][kc][t4] pairs (k,k+4)
__device__ float g_W2t[256 * 256];            // W2 tf32, row-major [h][k]

// ---------------- helpers --------------------------------------------------
__device__ __forceinline__ float tf32r(float v) {
    unsigned u;
    asm("cvt.rna.tf32.f32 %0, %1;" : "=r"(u) : "f"(v));
    return __uint_as_float(u);
}
__device__ __forceinline__ void mma_tf32(float d[4], float a0, float a1,
                                         float a2, float a3, float b0, float b1) {
    asm volatile(
        "mma.sync.aligned.m16n8k8.row.col.f32.tf32.tf32.f32 "
        "{%0,%1,%2,%3}, {%4,%5,%6,%7}, {%8,%9}, {%0,%1,%2,%3};"
        : "+f"(d[0]), "+f"(d[1]), "+f"(d[2]), "+f"(d[3])
        : "r"(__float_as_uint(a0)), "r"(__float_as_uint(a1)),
          "r"(__float_as_uint(a2)), "r"(__float_as_uint(a3)),
          "r"(__float_as_uint(b0)), "r"(__float_as_uint(b1)));
}
// byte offset of k within an interleaved row: float2 pairs (k, k+4) per 8-k block
#define IOFF(k) ((((k) >> 3) << 5) + (((k) & 3) << 3) + ((((k) >> 2) & 1) << 2))

// ---------------- prep kernels ---------------------------------------------
__global__ void prep_tr(const float* __restrict__ W1) {
    int i = blockIdx.x * 256 + threadIdx.x;   // 32768
    int c = i >> 8, h = i & 255;
    g_W1rT[i] = W1[h * 320 + 64 + c];
    g_W1cT[i] = W1[h * 320 + 192 + c];
}
__global__ void prep_np(const float* __restrict__ node, const float* __restrict__ b1) {
    int b = blockIdx.x >> 8, p = blockIdx.x & 255;
    int h = threadIdx.x;
    __shared__ float ns[128];
    if (h < 128) ns[h] = node[(b * 128 + h) * 256 + p];
    __syncthreads();
    float r = 0.f, c = 0.f;
#pragma unroll 16
    for (int k = 0; k < 128; k++) {
        float v = ns[k];
        r = fmaf(g_W1rT[k * 256 + h], v, r);
        c = fmaf(g_W1cT[k * 256 + h], v, c);
    }
    int o = (b * 256 + p) * 256 + h;
    g_R[o] = r + b1[h];
    g_C[o] = c;
}
__global__ void prep_w1(const float* __restrict__ W1) {
    int i = blockIdx.x * 256 + threadIdx.x;   // 8192: h*32 + kc*4 + t4
    int h = i >> 5, kc = (i >> 2) & 7, t4 = i & 3;
    int k = kc * 8 + t4;
    g_W1i[i] = make_float2(tf32r(W1[h * 320 + k]), tf32r(W1[h * 320 + k + 4]));
}
__global__ void prep_w2(const float* __restrict__ W2) {
    int i = blockIdx.x * 256 + threadIdx.x;   // 65536
    g_W2t[i] = tf32r(W2[i]);
}
__global__ void zero_out(float* __restrict__ out, const float* __restrict__ b3) {
    out[blockIdx.x * 256 + threadIdx.x] = b3[0];
}

// ---------------- main kernel ----------------------------------------------
// Row pitches chosen so pitch/4 mod 32 == 12 -> the 8 fragment rows hit 8
// distinct banks (old 8-mod-32 pitches gave 2-way conflicts on rows 4 apart).
#define PA 304                      // A row pitch (bytes), 76 words
#define PH 1072                     // h1 / W2 row pitch (bytes), 268 words
#define SW2   0                     // 128 h' rows
#define SA1   137216                // 64 px rows
#define SH1   156672                // 64 px rows
#define SW3   225280                // 128 f32
#define SB2   225792                // 128 f32
#define SMEM_TOTAL 226304

__global__ __launch_bounds__(256, 1)
void mlp_mma(const float* __restrict__ edge, const float* __restrict__ b2,
             const float* __restrict__ W3, float* __restrict__ out) {
    extern __shared__ char smem[];
    const int tid = threadIdx.x;
    const int wid = tid >> 5, lane = tid & 31;
    const int g = lane >> 2, t4 = lane & 3;
    const int hh = blockIdx.x & 1;

    // stage W2 half (tf32, interleaved) + W3/b2 halves
    for (int i = tid; i < 4096; i += 256) {       // i = h'(7b) * 32 + kc(5b)
        int hp = i >> 5, kc = i & 31;
        const float4* src = (const float4*)(g_W2t + (hh * 128 + hp) * 256 + kc * 8);
        float4 x = src[0], y = src[1];
        float4* dst = (float4*)(smem + SW2 + hp * PH + kc * 32);
        dst[0] = make_float4(x.x, y.x, x.y, y.y);
        dst[1] = make_float4(x.z, y.z, x.w, y.w);
    }
    if (tid < 128) {
        ((float*)(smem + SW3))[tid] = W3[hh * 128 + tid];
        ((float*)(smem + SB2))[tid] = b2[hh * 128 + tid];
    }

    const float* w3s = (const float*)(smem + SW3);
    const float* b2s = (const float*)(smem + SB2);
    const int hb1 = wid * 32;   // GEMM1: 32 h per warp (ni=4)
    const int hb2 = wid * 16;   // GEMM2: 16 h' per warp (ni=2)
    const int spx = tid & 63, se = tid >> 6;      // staging roles (4 e-chunks)

    // hoist GEMM1 B-fragments (tile-invariant): bb[ni][kc]
    float2 bb[4][8];
#pragma unroll
    for (int ni = 0; ni < 4; ni++)
#pragma unroll
        for (int kc = 0; kc < 8; kc++)
            bb[ni][kc] = g_W1i[(hb1 + ni * 8 + g) * 32 + kc * 4 + t4];

    // prologue: stage first edge tile
    {
        int t0 = blockIdx.x >> 1;
        int mt = t0 & 3, n = (t0 >> 2) & 255, b = t0 >> 10;
        const float* ep = edge +
            ((size_t)(b * 64 + se * 16) * 256 + n) * 256 + mt * 64 + spx;
        float v[16];
#pragma unroll
        for (int j = 0; j < 16; j++) v[j] = tf32r(ep[(size_t)j * 65536]);
        float4* dst = (float4*)(smem + SA1 + spx * PA + se * 64);
#pragma unroll
        for (int q = 0; q < 2; q++) {
            dst[2 * q]     = make_float4(v[8*q+0], v[8*q+4], v[8*q+1], v[8*q+5]);
            dst[2 * q + 1] = make_float4(v[8*q+2], v[8*q+6], v[8*q+3], v[8*q+7]);
        }
    }
    __syncthreads();

    for (int t = blockIdx.x >> 1; t < 4096; t += 74) {
        const int mt = t & 3, n = (t >> 2) & 255, b = t >> 10;
        const int m0 = mt * 64;

        // R row fragment for this (b, n)
        float2 Rv[4];
        {
            const float* Rb = g_R + ((b * 256 + n) << 8);
#pragma unroll
            for (int ni = 0; ni < 4; ni++)
                Rv[ni] = *(const float2*)(Rb + hb1 + ni * 8 + 2 * t4);
        }

        // ---- GEMM1: D1[64px, 256h] = A1 x W1e^T, K=64 ----
        float acc1[4][4][4];
#pragma unroll
        for (int mi = 0; mi < 4; mi++)
#pragma unroll
            for (int ni = 0; ni < 4; ni++)
#pragma unroll
                for (int q = 0; q < 4; q++) acc1[mi][ni][q] = 0.f;

#pragma unroll
        for (int kc = 0; kc < 8; kc++) {
            float2 p0[4], p1[4];
#pragma unroll
            for (int mi = 0; mi < 4; mi++) {
                p0[mi] = *(float2*)(smem + SA1 + (mi * 16 + g) * PA + kc * 32 + t4 * 8);
                p1[mi] = *(float2*)(smem + SA1 + (mi * 16 + g + 8) * PA + kc * 32 + t4 * 8);
            }
#pragma unroll
            for (int ni = 0; ni < 4; ni++)
#pragma unroll
                for (int mi = 0; mi < 4; mi++)
                    mma_tf32(acc1[mi][ni], p0[mi].x, p1[mi].x, p0[mi].y, p1[mi].y,
                             bb[ni][kc].x, bb[ni][kc].y);
        }

        // ---- epilogue 1: relu(D1 + R + C) -> h1 (tf32) in SMEM ----
        {
            const float* Cb = g_C + ((size_t)(b * 256 + m0) << 8);
#pragma unroll
            for (int mi = 0; mi < 4; mi++)
#pragma unroll
                for (int ni = 0; ni < 4; ni++) {
                    int h = hb1 + ni * 8 + 2 * t4;
                    int px0 = mi * 16 + g, px1 = px0 + 8;
                    float2 C0 = *(const float2*)(Cb + (px0 << 8) + h);
                    float2 C1 = *(const float2*)(Cb + (px1 << 8) + h);
                    float v00 = fmaxf(acc1[mi][ni][0] + Rv[ni].x + C0.x, 0.f);
                    float v01 = fmaxf(acc1[mi][ni][1] + Rv[ni].y + C0.y, 0.f);
                    float v10 = fmaxf(acc1[mi][ni][2] + Rv[ni].x + C1.x, 0.f);
                    float v11 = fmaxf(acc1[mi][ni][3] + Rv[ni].y + C1.y, 0.f);
                    unsigned o0 = SH1 + px0 * PH, o1 = SH1 + px1 * PH;
                    unsigned kh = IOFF(h), kh1 = IOFF(h + 1);
                    *(float*)(smem + o0 + kh)  = tf32r(v00);
                    *(float*)(smem + o0 + kh1) = tf32r(v01);
                    *(float*)(smem + o1 + kh)  = tf32r(v10);
                    *(float*)(smem + o1 + kh1) = tf32r(v11);
                }
        }
        __syncthreads();   // h1 visible; A tile now free for re-staging

        // ---- prefetch next tile's edge into registers ----
        float ev[16];
        const int tn = t + 74;
        if (tn < 4096) {
            int mtn = tn & 3, nn = (tn >> 2) & 255, bn = tn >> 10;
            const float* ep = edge +
                ((size_t)(bn * 64 + se * 16) * 256 + nn) * 256 + mtn * 64 + spx;
#pragma unroll
            for (int j = 0; j < 16; j++) ev[j] = ep[(size_t)j * 65536];
        }

        // ---- GEMM2: D2[64px, 16h'] = h1 x W2half^T, K=256 ----
        float acc2[4][2][4];
#pragma unroll
        for (int mi = 0; mi < 4; mi++)
#pragma unroll
            for (int ni = 0; ni < 2; ni++)
#pragma unroll
                for (int q = 0; q < 4; q++) acc2[mi][ni][q] = 0.f;

#pragma unroll 4
        for (int kc = 0; kc < 32; kc++) {
            float2 p0[4], p1[4];
#pragma unroll
            for (int mi = 0; mi < 4; mi++) {
                p0[mi] = *(float2*)(smem + SH1 + (mi * 16 + g) * PH + kc * 32 + t4 * 8);
                p1[mi] = *(float2*)(smem + SH1 + (mi * 16 + g + 8) * PH + kc * 32 + t4 * 8);
            }
            float2 wb[2];
#pragma unroll
            for (int ni = 0; ni < 2; ni++)
                wb[ni] = *(float2*)(smem + SW2 + (hb2 + ni * 8 + g) * PH + kc * 32 + t4 * 8);
#pragma unroll
            for (int ni = 0; ni < 2; ni++)
#pragma unroll
                for (int mi = 0; mi < 4; mi++)
                    mma_tf32(acc2[mi][ni], p0[mi].x, p1[mi].x, p0[mi].y, p1[mi].y,
                             wb[ni].x, wb[ni].y);
        }

        // ---- epilogue 2 + layer 3 + atomic combine ----
        {
            float po[4][2];
#pragma unroll
            for (int mi = 0; mi < 4; mi++) { po[mi][0] = 0.f; po[mi][1] = 0.f; }
#pragma unroll
            for (int mi = 0; mi < 4; mi++)
#pragma unroll
                for (int ni = 0; ni < 2; ni++) {
                    int h = hb2 + ni * 8 + 2 * t4;
                    float w3a = w3s[h], w3b = w3s[h + 1];
                    float ba = b2s[h], bbv = b2s[h + 1];
                    po[mi][0] = fmaf(w3a, fmaxf(acc2[mi][ni][0] + ba, 0.f), po[mi][0]);
                    po[mi][0] = fmaf(w3b, fmaxf(acc2[mi][ni][1] + bbv, 0.f), po[mi][0]);
                    po[mi][1] = fmaf(w3a, fmaxf(acc2[mi][ni][2] + ba, 0.f), po[mi][1]);
                    po[mi][1] = fmaf(w3b, fmaxf(acc2[mi][ni][3] + bbv, 0.f), po[mi][1]);
                }
#pragma unroll
            for (int mi = 0; mi < 4; mi++)
#pragma unroll
                for (int r = 0; r < 2; r++) {
                    po[mi][r] += __shfl_xor_sync(0xffffffffu, po[mi][r], 1);
                    po[mi][r] += __shfl_xor_sync(0xffffffffu, po[mi][r], 2);
                }
            if (t4 == 0) {
                int ob = ((b * 256 + n) << 8) + m0;
#pragma unroll
                for (int mi = 0; mi < 4; mi++) {
                    atomicAdd(out + ob + mi * 16 + g, po[mi][0]);
                    atomicAdd(out + ob + mi * 16 + g + 8, po[mi][1]);
                }
            }
        }

        // ---- store prefetched edge into the (now free) A buffer ----
        if (tn < 4096) {
            float4* dst = (float4*)(smem + SA1 + spx * PA + se * 64);
#pragma unroll
            for (int q = 0; q < 2; q++) {
                dst[2 * q]     = make_float4(tf32r(ev[8*q+0]), tf32r(ev[8*q+4]),
                                             tf32r(ev[8*q+1]), tf32r(ev[8*q+5]));
                dst[2 * q + 1] = make_float4(tf32r(ev[8*q+2]), tf32r(ev[8*q+6]),
                                             tf32r(ev[8*q+3]), tf32r(ev[8*q+7]));
            }
        }
        __syncthreads();
    }
}

extern "C" void kernel_launch(void* const* d_in, const int* in_sizes, int n_in,
                              void* d_out, int out_size) {
    const float* edge = (const float*)d_in[0];
    const float* node = (const float*)d_in[1];
    const float* W1   = (const float*)d_in[2];
    const float* b1   = (const float*)d_in[3];
    const float* W2   = (const float*)d_in[4];
    const float* b2   = (const float*)d_in[5];
    const float* W3   = (const float*)d_in[6];
    const float* b3   = (const float*)d_in[7];
    float* out = (float*)d_out;

    cudaFuncSetAttribute(mlp_mma, cudaFuncAttributeMaxDynamicSharedMemorySize,
                         SMEM_TOTAL);

    prep_tr<<<128, 256>>>(W1);
    prep_np<<<1024, 256>>>(node, b1);
    prep_w1<<<32, 256>>>(W1);
    prep_w2<<<256, 256>>>(W2);
    zero_out<<<1024, 256>>>(out, b3);
    mlp_mma<<<148, 256, SMEM_TOTAL>>>(edge, b2, W3, out);
}